// round 1
// baseline (speedup 1.0000x reference)
#include <cuda_runtime.h>
#include <math.h>

// Problem constants
//  B=2048, T_SRC=T_TGT=32, D=512, 4D=2048, D_TGT=80, L=2
#define NB      2048
#define NT      32
#define ND      512
#define NG      2048   // 4*D
#define NOUT    80

// ---------------- static device scratch (no runtime allocation) ----------------
__device__ float g_Xemb[32 * 2048 * 512];   // encoder embeddings, time-major (T,B,D)
__device__ float g_H0[2048 * 512];
__device__ float g_H1[2048 * 512];
__device__ float g_C0[2048 * 512];
__device__ float g_C1[2048 * 512];
__device__ float g_Xd0[2048 * 512];         // decoder prev-token embedding
__device__ float g_gates[2048 * 2048];      // gate pre-activations for one cell

// ---------------------------------------------------------------------------
// GEMM: gates[m,n] = sum_{k<512} Ax[m,k]*Wih[n,k] + sum_{k<512} Ah[m,k]*Whh[n,k]
//                    + bih[n] + bhh[n]
// M = N = 2048, effective K = 1024 (two 512 halves with different pointers).
// Classic 128x128 tile, BK=8, 256 threads, 8x8 per-thread microtile, fp32.
// ---------------------------------------------------------------------------
__global__ __launch_bounds__(256, 2)
void lstm_gates_gemm(const float* __restrict__ Ax, const float* __restrict__ Ah,
                     const float* __restrict__ Wih, const float* __restrict__ Whh,
                     const float* __restrict__ bih, const float* __restrict__ bhh,
                     float* __restrict__ gates)
{
    __shared__ float As[8][128];
    __shared__ float Bs[8][128];

    const int tid  = threadIdx.x;
    const int lrow = tid >> 1;            // 0..127
    const int lcol = (tid & 1) << 2;      // 0 or 4
    const int tx   = tid & 15;            // 0..15
    const int ty   = tid >> 4;            // 0..15
    const int gm   = blockIdx.y * 128;
    const int gn   = blockIdx.x * 128;

    float acc[8][8];
#pragma unroll
    for (int i = 0; i < 8; ++i)
#pragma unroll
        for (int j = 0; j < 8; ++j) acc[i][j] = 0.0f;

    const float* Arow0 = Ax  + (long)(gm + lrow) * ND + lcol;
    const float* Arow1 = Ah  + (long)(gm + lrow) * ND + lcol;
    const float* Wrow0 = Wih + (long)(gn + lrow) * ND + lcol;
    const float* Wrow1 = Whh + (long)(gn + lrow) * ND + lcol;

    for (int kt = 0; kt < 128; ++kt) {
        const int kk = kt << 3;                   // global k (0..1016)
        const float* Ap;
        const float* Wp;
        if (kk < 512) { Ap = Arow0 + kk;        Wp = Wrow0 + kk; }
        else          { Ap = Arow1 + (kk - 512); Wp = Wrow1 + (kk - 512); }

        float4 av = *reinterpret_cast<const float4*>(Ap);
        float4 wv = *reinterpret_cast<const float4*>(Wp);

        __syncthreads();   // prior compute done before overwriting smem
        As[lcol + 0][lrow] = av.x;
        As[lcol + 1][lrow] = av.y;
        As[lcol + 2][lrow] = av.z;
        As[lcol + 3][lrow] = av.w;
        Bs[lcol + 0][lrow] = wv.x;
        Bs[lcol + 1][lrow] = wv.y;
        Bs[lcol + 2][lrow] = wv.z;
        Bs[lcol + 3][lrow] = wv.w;
        __syncthreads();

#pragma unroll
        for (int k = 0; k < 8; ++k) {
            float a[8], b[8];
#pragma unroll
            for (int i = 0; i < 8; ++i) a[i] = As[k][ty * 8 + i];
#pragma unroll
            for (int j = 0; j < 8; ++j) b[j] = Bs[k][tx * 8 + j];
#pragma unroll
            for (int i = 0; i < 8; ++i)
#pragma unroll
                for (int j = 0; j < 8; ++j)
                    acc[i][j] = fmaf(a[i], b[j], acc[i][j]);
        }
    }

    // epilogue: add biases, store
    const int n0 = gn + tx * 8;
    float bsum[8];
#pragma unroll
    for (int j = 0; j < 8; ++j) bsum[j] = bih[n0 + j] + bhh[n0 + j];

#pragma unroll
    for (int i = 0; i < 8; ++i) {
        const int m = gm + ty * 8 + i;
        float* gr = gates + (long)m * NG + n0;
#pragma unroll
        for (int j = 0; j < 8; ++j) gr[j] = acc[i][j] + bsum[j];
    }
}

// ---------------------------------------------------------------------------
// Elementwise LSTM cell update: reads gates (B x 4D), updates C and H in place.
// gate layout along n: [i(0:512) f(512:1024) g(1024:1536) o(1536:2048)]
// ---------------------------------------------------------------------------
__device__ __forceinline__ float sigmoidf_acc(float x) {
    return 1.0f / (1.0f + expf(-x));
}

__global__ __launch_bounds__(256)
void lstm_elem(const float* __restrict__ gates,
               float* __restrict__ C, float* __restrict__ H)
{
    const int idx = blockIdx.x * 256 + threadIdx.x;     // 0 .. B*D-1
    if (idx >= NB * ND) return;
    const int b = idx >> 9;
    const int d = idx & 511;
    const float* g = gates + (long)b * NG;
    const float iv = g[d];
    const float fv = g[512 + d];
    const float gv = g[1024 + d];
    const float ov = g[1536 + d];
    const float cn = sigmoidf_acc(fv) * C[idx] + sigmoidf_acc(iv) * tanhf(gv);
    C[idx] = cn;
    H[idx] = sigmoidf_acc(ov) * tanhf(cn);
}

// ---------------------------------------------------------------------------
// Encoder embedding gather: Xemb[t,b,:] = enc_emb[src[b,t]]
// ---------------------------------------------------------------------------
__global__ void embed_src_kernel(const int* __restrict__ src,
                                 const float* __restrict__ emb,
                                 float* __restrict__ X)
{
    const long q = (long)blockIdx.x * 256 + threadIdx.x;   // float4 index
    if (q >= 32L * NB * (ND / 4)) return;
    const int  c4 = (int)(q & 127) << 2;
    const long tb = q >> 7;                  // t*B + b
    const int  b  = (int)(tb & (NB - 1));
    const int  t  = (int)(tb >> 11);
    const int  tok = src[b * NT + t];
    const float4 v = *reinterpret_cast<const float4*>(&emb[(long)tok * ND + c4]);
    *reinterpret_cast<float4*>(&X[tb * ND + c4]) = v;
}

// Decoder initial token: Xd0[b,:] = dec_emb[tgt[b,0]]
__global__ void embed_tgt0_kernel(const int* __restrict__ tgt,
                                  const float* __restrict__ emb,
                                  float* __restrict__ Xd0)
{
    const int q = blockIdx.x * 256 + threadIdx.x;   // float4 index over B*128
    if (q >= NB * (ND / 4)) return;
    const int b  = q >> 7;
    const int c4 = (q & 127) << 2;
    const int tok = tgt[b * NT];
    const float4 v = *reinterpret_cast<const float4*>(&emb[(long)tok * ND + c4]);
    *reinterpret_cast<float4*>(&Xd0[(long)b * ND + c4]) = v;
}

// ---------------------------------------------------------------------------
// Decoder head: logits = H1 @ post_W^T + post_b ; argmax (first max) ;
// write logits to out[b, t, :] ; Xd0[b,:] = dec_emb[pred]
// One block = 8 batch rows, 256 threads.
// ---------------------------------------------------------------------------
__global__ __launch_bounds__(256)
void dec_logits_kernel(const float* __restrict__ H1,
                       const float* __restrict__ postW,
                       const float* __restrict__ postb,
                       const float* __restrict__ dec_emb,
                       float* __restrict__ out,
                       float* __restrict__ Xd0,
                       int t)
{
    __shared__ float hs[8][516];     // padded to avoid bank conflicts
    __shared__ float Ws[80][65];     // one 64-wide K chunk of post_W, padded
    __shared__ float lg[8][80];
    __shared__ int   pred[8];

    const int tid = threadIdx.x;
    const int b0  = blockIdx.x * 8;

    // load 8 H rows into smem (1024 float4)
    for (int q = tid; q < 1024; q += 256) {
        const int r  = q >> 7;
        const int c4 = (q & 127) << 2;
        const float4 v = *reinterpret_cast<const float4*>(&H1[(long)(b0 + r) * ND + c4]);
        hs[r][c4 + 0] = v.x; hs[r][c4 + 1] = v.y;
        hs[r][c4 + 2] = v.z; hs[r][c4 + 3] = v.w;
    }

    const int n  = tid % 80;     // output class (valid when tid < 240)
    const int rs = tid / 80;     // row group: 0 -> rows 0..2, 1 -> 3..5, 2 -> 6..7
    const int r0 = rs * 3;
    const int r1 = r0 + 1;
    const int r2 = (rs == 2) ? (r0 + 1) : (r0 + 2);   // dup when group has 2 rows
    float acc0 = 0.0f, acc1 = 0.0f, acc2 = 0.0f;

    for (int c = 0; c < 8; ++c) {         // 8 K-chunks of 64
        __syncthreads();
        // load Ws chunk: 80 x 64 floats = 1280 float4
        for (int q = tid; q < 1280; q += 256) {
            const int wr = q >> 4;
            const int wc = (q & 15) << 2;
            const float4 v = *reinterpret_cast<const float4*>(
                &postW[(long)wr * ND + c * 64 + wc]);
            Ws[wr][wc + 0] = v.x; Ws[wr][wc + 1] = v.y;
            Ws[wr][wc + 2] = v.z; Ws[wr][wc + 3] = v.w;
        }
        __syncthreads();
        if (tid < 240) {
            const int kb = c * 64;
#pragma unroll 8
            for (int j = 0; j < 64; ++j) {
                const float w = Ws[n][j];
                acc0 = fmaf(hs[r0][kb + j], w, acc0);
                acc1 = fmaf(hs[r1][kb + j], w, acc1);
                acc2 = fmaf(hs[r2][kb + j], w, acc2);
            }
        }
    }
    if (tid < 240) {
        const float pb = postb[n];
        lg[r0][n] = acc0 + pb;
        lg[r1][n] = acc1 + pb;
        if (rs < 2) lg[r2][n] = acc2 + pb;
    }
    __syncthreads();

    // per-row argmax (first occurrence of max, matching jnp.argmax)
    if (tid < 8) {
        float best = lg[tid][0];
        int   bi   = 0;
        for (int k = 1; k < 80; ++k) {
            const float v = lg[tid][k];
            if (v > best) { best = v; bi = k; }
        }
        pred[tid] = bi;
    }
    __syncthreads();

    // write logits to out[b, t, :]
    for (int q = tid; q < 8 * 80; q += 256) {
        const int r  = q / 80;
        const int nn = q % 80;
        out[((long)(b0 + r) * NT + t) * NOUT + nn] = lg[r][nn];
    }
    // feed back embedding of prediction
    for (int q = tid; q < 1024; q += 256) {
        const int r  = q >> 7;
        const int c4 = (q & 127) << 2;
        const float4 v = *reinterpret_cast<const float4*>(
            &dec_emb[(long)pred[r] * ND + c4]);
        *reinterpret_cast<float4*>(&Xd0[(long)(b0 + r) * ND + c4]) = v;
    }
}

// ---------------------------------------------------------------------------
extern "C" void kernel_launch(void* const* d_in, const int* in_sizes, int n_in,
                              void* d_out, int out_size)
{
    const int*   src     = (const int*)  d_in[0];
    const int*   tgt     = (const int*)  d_in[1];
    const float* enc_emb = (const float*)d_in[2];
    const float* dec_emb = (const float*)d_in[3];
    const float* enc_Wih = (const float*)d_in[4];
    const float* enc_Whh = (const float*)d_in[5];
    const float* enc_bih = (const float*)d_in[6];
    const float* enc_bhh = (const float*)d_in[7];
    const float* dec_Wih = (const float*)d_in[8];
    const float* dec_Whh = (const float*)d_in[9];
    const float* dec_bih = (const float*)d_in[10];
    const float* dec_bhh = (const float*)d_in[11];
    const float* post_W  = (const float*)d_in[12];
    const float* post_b  = (const float*)d_in[13];
    float*       out     = (float*)d_out;

    float *Xemb, *H0, *H1, *C0, *C1, *Xd0, *gates;
    cudaGetSymbolAddress((void**)&Xemb,  g_Xemb);
    cudaGetSymbolAddress((void**)&H0,    g_H0);
    cudaGetSymbolAddress((void**)&H1,    g_H1);
    cudaGetSymbolAddress((void**)&C0,    g_C0);
    cudaGetSymbolAddress((void**)&C1,    g_C1);
    cudaGetSymbolAddress((void**)&Xd0,   g_Xd0);
    cudaGetSymbolAddress((void**)&gates, g_gates);

    const size_t stateBytes = (size_t)NB * ND * sizeof(float);
    cudaMemsetAsync(H0, 0, stateBytes);
    cudaMemsetAsync(H1, 0, stateBytes);
    cudaMemsetAsync(C0, 0, stateBytes);
    cudaMemsetAsync(C1, 0, stateBytes);

    // gather all encoder embeddings (time-major)
    {
        const long nq = 32L * NB * (ND / 4);
        embed_src_kernel<<<(unsigned)((nq + 255) / 256), 256>>>(src, enc_emb, Xemb);
    }

    const long WBLK = (long)NG * ND;   // per-layer weight block (4D x D)
    const dim3 gemmGrid(16, 16);
    const int  elemBlocks = (NB * ND + 255) / 256;

    // ---------------- encoder ----------------
    for (int t = 0; t < NT; ++t) {
        lstm_gates_gemm<<<gemmGrid, 256>>>(Xemb + (long)t * NB * ND, H0,
                                           enc_Wih, enc_Whh,
                                           enc_bih, enc_bhh, gates);
        lstm_elem<<<elemBlocks, 256>>>(gates, C0, H0);

        lstm_gates_gemm<<<gemmGrid, 256>>>(H0, H1,
                                           enc_Wih + WBLK, enc_Whh + WBLK,
                                           enc_bih + NG,   enc_bhh + NG, gates);
        lstm_elem<<<elemBlocks, 256>>>(gates, C1, H1);
    }

    // ---------------- decoder ----------------
    embed_tgt0_kernel<<<(NB * (ND / 4) + 255) / 256, 256>>>(tgt, dec_emb, Xd0);

    for (int t = 0; t < NT; ++t) {
        lstm_gates_gemm<<<gemmGrid, 256>>>(Xd0, H0,
                                           dec_Wih, dec_Whh,
                                           dec_bih, dec_bhh, gates);
        lstm_elem<<<elemBlocks, 256>>>(gates, C0, H0);

        lstm_gates_gemm<<<gemmGrid, 256>>>(H0, H1,
                                           dec_Wih + WBLK, dec_Whh + WBLK,
                                           dec_bih + NG,   dec_bhh + NG, gates);
        lstm_elem<<<elemBlocks, 256>>>(gates, C1, H1);

        dec_logits_kernel<<<NB / 8, 256>>>(H1, post_W, post_b, dec_emb,
                                           out, Xd0, t);
    }
}